// round 17
// baseline (speedup 1.0000x reference)
#include <cuda_runtime.h>
#include <cuda_fp16.h>
#include <cstdint>

// GIN (N=8192, D=256), 2 layers. R17: TWO kernels total.
// layer1: converts W1/W2 fp32->fp16 in-CTA (no separate wconv kernel),
//         publishes fp16 weights to global for layer2, input from fp32 x.
// layer2: cp.async fp16 weights (published by layer1), input fp16 B.
// Fused MLP per layer: H=relu(A@W1^T+b1) in smem, then out=H@W2^T+b2.
// Single-pass fp16 HMMA, fp32 accum. eps!=0 fallback paths preserved.

#define GN 8192
#define GD 256

// ---------------- scratch (__device__ globals; no allocation allowed) ----------------
__device__ __half g_B[GN * GD];
__device__ __half g_W1h[GD * GD];
__device__ __half g_W2h[GD * GD];
__device__ float g_F[GN * GD];

// ---------------- PTX helpers (sm_80-era, compute_103-legal) ----------------
__device__ __forceinline__ uint32_t smem_u32(const void* p) {
    uint32_t a;
    asm("{ .reg .u64 t; cvta.to.shared.u64 t, %1; cvt.u32.u64 %0, t; }"
        : "=r"(a) : "l"(p));
    return a;
}

__device__ __forceinline__ void cp_async16(uint32_t s, const void* g) {
    asm volatile("cp.async.cg.shared.global [%0], [%1], 16;" :: "r"(s), "l"(g));
}
#define CP_COMMIT() asm volatile("cp.async.commit_group;" ::: "memory")
#define CP_WAIT(n)  asm volatile("cp.async.wait_group %0;" :: "n"(n) : "memory")

__device__ __forceinline__ void ldsm_x4(uint32_t* r, uint32_t addr) {
    asm volatile("ldmatrix.sync.aligned.m8n8.x4.shared.b16 {%0,%1,%2,%3}, [%4];"
                 : "=r"(r[0]), "=r"(r[1]), "=r"(r[2]), "=r"(r[3]) : "r"(addr));
}

__device__ __forceinline__ void mma16816(float* d, const uint32_t* a,
                                         const uint32_t* b) {
    asm volatile(
        "mma.sync.aligned.m16n8k16.row.col.f32.f16.f16.f32 "
        "{%0,%1,%2,%3}, {%4,%5,%6,%7}, {%8,%9}, {%0,%1,%2,%3};"
        : "+f"(d[0]), "+f"(d[1]), "+f"(d[2]), "+f"(d[3])
        : "r"(a[0]), "r"(a[1]), "r"(a[2]), "r"(a[3]), "r"(b[0]), "r"(b[1]));
}

// convert 2 float4 (8 fp32) -> 8 fp16 packed in uint4
__device__ __forceinline__ uint4 cvt8(float4 a, float4 b) {
    __half h[8];
    h[0] = __float2half_rn(a.x); h[1] = __float2half_rn(a.y);
    h[2] = __float2half_rn(a.z); h[3] = __float2half_rn(a.w);
    h[4] = __float2half_rn(b.x); h[5] = __float2half_rn(b.y);
    h[6] = __float2half_rn(b.z); h[7] = __float2half_rn(b.w);
    return *(uint4*)h;
}

// ---------------- tiling ----------------
#define BM 64
#define LDT 264                          // padded row stride (fp16)
#define LDTB (LDT * 2)                   // 528 bytes
#define A_BYTES (BM * LDTB)              // 33792
#define W_BYTES (GD * LDTB)              // 135168
#define OFF_A 0
#define OFF_W A_BYTES
#define OFF_H (A_BYTES + W_BYTES)        // 168960
#define SMEM_TOTAL (OFF_H + A_BYTES)     // 202752

struct FragP {
    uint32_t a[2][4];    // two m16 tiles
    uint32_t w[4][4];    // four n16 tiles (warp covers 64 N-cols)
};

// Fused layer. grid 128; 256 thr = 8 warps in 2(m) x 4(n); warp tile 32x64.
// FIRST: fp32 weights converted in-CTA + published fp16; input from fp32 xf.
// else : fp16 weights via cp.async; input fp16 inh (or agg from srcF).
// LAST : write fp32 Of; else fp16 Oh (+ fp32 Of when eps!=0).
template <bool FIRST, bool LAST>
__global__ void __launch_bounds__(256, 1)
mlp_layer(const float* __restrict__ xf, const __half* __restrict__ inh,
          const float* __restrict__ srcF, const float* __restrict__ adj,
          const float* __restrict__ W1f, const float* __restrict__ W2f,
          const __half* __restrict__ W1h, const __half* __restrict__ W2h,
          __half* __restrict__ W1pub, __half* __restrict__ W2pub,
          const float* __restrict__ b1, const float* __restrict__ b2,
          const float* __restrict__ eps,
          __half* __restrict__ Oh, float* __restrict__ Of) {
    extern __shared__ __align__(16) char smem[];
    const uint32_t sb = smem_u32(smem);
    const int tid = threadIdx.x;
    const int wid = tid >> 5;
    const int lane = tid & 31;
    const int warp_m = wid & 1;          // 2 warps along M (32 rows)
    const int warp_n = wid >> 1;         // 4 warps along N (64 cols)
    const int bm = blockIdx.x * BM;

    const float e = __ldg(eps);

    // fp16 W via cp.async (layer >= 2)
    auto load_W_half_async = [&](const __half* W, int g) {
#pragma unroll
        for (int it = 0; it < 16; it++) {
            const int idx = tid + it * 256;
            const int row = idx >> 4;
            const int q = idx & 15;
            cp_async16(sb + OFF_W + (uint32_t)(row * LDTB + g * 256 + q * 16),
                       W + (size_t)row * GD + g * 128 + q * 8);
        }
    };
    // fp32 W -> fp16 smem (layer 1); full 256x256
    auto conv_W_full = [&](const float* W) {
#pragma unroll
        for (int it = 0; it < 32; it++) {
            const int idx = tid + it * 256;          // 0..8191
            const int row = idx >> 5;
            const int q = idx & 31;
            const float4* src = (const float4*)(W + (size_t)row * GD + q * 8);
            *(uint4*)(smem + OFF_W + row * LDTB + q * 16) = cvt8(src[0], src[1]);
        }
    };

    // ---------------- prologue ----------------
    if (FIRST) {
        // publish this CTA's 2-row share of fp16 W1/W2 for layer 2
        {
            const int prow = 2 * blockIdx.x + (tid >> 7);   // 0..255
            const int pcol = (tid & 127) * 2;
            float2 w1 = *(const float2*)(W1f + (size_t)prow * GD + pcol);
            float2 w2 = *(const float2*)(W2f + (size_t)prow * GD + pcol);
            __half2 p1, p2;
            p1.x = __float2half_rn(w1.x); p1.y = __float2half_rn(w1.y);
            p2.x = __float2half_rn(w2.x); p2.y = __float2half_rn(w2.y);
            *(__half2*)(W1pub + (size_t)prow * GD + pcol) = p1;
            *(__half2*)(W2pub + (size_t)prow * GD + pcol) = p2;
        }
        conv_W_full(W1f);
    } else {
        load_W_half_async(W1h, 0); CP_COMMIT();
        load_W_half_async(W1h, 1); CP_COMMIT();
    }

    if (e == 0.0f) {
        if (FIRST) {
            // fp32 x -> fp16 smem A
            const float4* x4 = (const float4*)(xf + (size_t)bm * GD);
#pragma unroll
            for (int it = 0; it < 8; it++) {
                const int idx = tid + it * 256;      // 0..2047
                const int row = idx >> 5;
                const int q = idx & 31;
                float4 a = x4[(size_t)idx * 2];
                float4 b = x4[(size_t)idx * 2 + 1];
                *(uint4*)(smem + OFF_A + row * LDTB + q * 16) = cvt8(a, b);
            }
        } else {
            const uint4* i4 = (const uint4*)(inh + (size_t)bm * GD);
#pragma unroll
            for (int it = 0; it < 8; it++) {
                const int idx = tid + it * 256;
                const int row = idx >> 5;
                const int q = idx & 31;
                *(uint4*)(smem + OFF_A + row * LDTB + q * 16) = i4[idx];
            }
        }
    } else {
        // fallback: fp16(src + e * adj @ src) for this CTA's rows
        const float* src = FIRST ? xf : srcF;
        const int col = tid;
        for (int rr = 0; rr < BM; rr++) {
            const int row = bm + rr;
            float s = 0.0f;
            const float* arow = adj + (size_t)row * GN;
            for (int k = 0; k < GN; k++) s += arow[k] * src[(size_t)k * GD + col];
            const float v = src[(size_t)row * GD + col] + e * s;
            *(__half*)(smem + OFF_A + rr * LDTB + col * 2) = __float2half_rn(v);
        }
    }

    // ---- fragment addressing ----
    const uint32_t a_rel =
        (uint32_t)((warp_m * 32 + (lane & 15)) * LDTB) + (uint32_t)(lane >> 4) * 16;
    const int mmat = lane >> 3;
    const uint32_t w_rel =
        (uint32_t)((warp_n * 64 + (lane & 7) + ((mmat >> 1) & 1) * 8) * LDTB) +
        (uint32_t)(mmat & 1) * 16;

    float acc[2][8][4];

    auto ld_frags = [&](FragP& f, uint32_t abase, uint32_t wbase, int k16) {
        const uint32_t kadd = (uint32_t)k16 * 32;
#pragma unroll
        for (int mi = 0; mi < 2; mi++)
            ldsm_x4(f.a[mi], abase + a_rel + kadd + (uint32_t)(mi * 16 * LDTB));
#pragma unroll
        for (int ni = 0; ni < 4; ni++)
            ldsm_x4(f.w[ni], wbase + w_rel + kadd + (uint32_t)(ni * 16 * LDTB));
    };

    auto run8 = [&](uint32_t abase, uint32_t wbase, int k0) {
        FragP fr[2];
        ld_frags(fr[0], abase, wbase, k0);
#pragma unroll
        for (int i = 0; i < 8; i++) {
            const int cb = i & 1;
            if (i < 7) ld_frags(fr[cb ^ 1], abase, wbase, k0 + i + 1);
#pragma unroll
            for (int mi = 0; mi < 2; mi++)
#pragma unroll
                for (int n8 = 0; n8 < 8; n8++)
                    mma16816(acc[mi][n8], fr[cb].a[mi],
                             &fr[cb].w[n8 >> 1][(n8 & 1) * 2]);
        }
    };

#pragma unroll
    for (int i = 0; i < 2; i++)
#pragma unroll
        for (int j = 0; j < 8; j++)
#pragma unroll
            for (int k = 0; k < 4; k++) acc[i][j][k] = 0.0f;

    // ================= phase 1: H = relu(A @ W1^T + b1) =================
    if (FIRST) {
        __syncthreads();                 // A + W1 stores visible
        run8(sb + OFF_A, sb + OFF_W, 0);
        run8(sb + OFF_A, sb + OFF_W, 8);
    } else {
        CP_WAIT(1);
        __syncthreads();
        run8(sb + OFF_A, sb + OFF_W, 0);
        CP_WAIT(0);
        __syncthreads();
        run8(sb + OFF_A, sb + OFF_W, 8);
    }
    __syncthreads();                     // all warps done reading W1 / A

    // start W2 into the W slot (overwrites W1)
    if (!FIRST) {
        load_W_half_async(W2h, 0); CP_COMMIT();
        load_W_half_async(W2h, 1); CP_COMMIT();
    } else {
        conv_W_full(W2f);                // LDG fp32 -> cvt -> STS
    }

    // store H (bias + relu + fp16) into smem H slot
    const int r = lane >> 2;
    const int c2 = (lane & 3) * 2;
#pragma unroll
    for (int mi = 0; mi < 2; mi++) {
#pragma unroll
        for (int half = 0; half < 2; half++) {
            const int rowl = warp_m * 32 + mi * 16 + r + half * 8;
#pragma unroll
            for (int n8 = 0; n8 < 8; n8++) {
                const int n = warp_n * 64 + n8 * 8 + c2;
                float v0 = acc[mi][n8][half * 2 + 0] + __ldg(b1 + n);
                float v1 = acc[mi][n8][half * 2 + 1] + __ldg(b1 + n + 1);
                v0 = fmaxf(v0, 0.0f);
                v1 = fmaxf(v1, 0.0f);
                __half2 hp;
                hp.x = __float2half_rn(v0);
                hp.y = __float2half_rn(v1);
                *(__half2*)(smem + OFF_H + rowl * LDTB + n * 2) = hp;
            }
        }
    }

#pragma unroll
    for (int i = 0; i < 2; i++)
#pragma unroll
        for (int j = 0; j < 8; j++)
#pragma unroll
            for (int k = 0; k < 4; k++) acc[i][j][k] = 0.0f;

    // ================= phase 2: out = H @ W2^T + b2 =================
    if (FIRST) {
        __syncthreads();                 // W2 + H stores visible
        run8(sb + OFF_H, sb + OFF_W, 0);
        run8(sb + OFF_H, sb + OFF_W, 8);
    } else {
        CP_WAIT(1);
        __syncthreads();
        run8(sb + OFF_H, sb + OFF_W, 0);
        CP_WAIT(0);
        __syncthreads();
        run8(sb + OFF_H, sb + OFF_W, 8);
    }

    // ---- epilogue ----
    const bool do_f32 = (!LAST) && (e != 0.0f);
#pragma unroll
    for (int mi = 0; mi < 2; mi++) {
#pragma unroll
        for (int half = 0; half < 2; half++) {
            const int m = bm + warp_m * 32 + mi * 16 + r + half * 8;
#pragma unroll
            for (int n8 = 0; n8 < 8; n8++) {
                const int n = warp_n * 64 + n8 * 8 + c2;
                float v0 = acc[mi][n8][half * 2 + 0] + __ldg(b2 + n);
                float v1 = acc[mi][n8][half * 2 + 1] + __ldg(b2 + n + 1);
                if (LAST) {
                    *(float2*)(Of + (size_t)m * GD + n) = make_float2(v0, v1);
                } else {
                    __half2 hp;
                    hp.x = __float2half_rn(v0);
                    hp.y = __float2half_rn(v1);
                    *(__half2*)(Oh + (size_t)m * GD + n) = hp;
                    if (do_f32)
                        *(float2*)(Of + (size_t)m * GD + n) = make_float2(v0, v1);
                }
            }
        }
    }
}

// ---------------------------------------------------------------------------
// kernel_launch
// ---------------------------------------------------------------------------
extern "C" void kernel_launch(void* const* d_in, const int* in_sizes, int n_in,
                              void* d_out, int out_size) {
    const float* x   = (const float*)d_in[0];
    const float* adj = (const float*)d_in[1];
    const float* W1  = (const float*)d_in[2];
    const float* b1  = (const float*)d_in[3];
    const float* W2  = (const float*)d_in[4];
    const float* b2  = (const float*)d_in[5];
    const float* eps = (const float*)d_in[6];
    float* out = (float*)d_out;

    __half *B, *W1h, *W2h;
    float* F;
    cudaGetSymbolAddress((void**)&B, g_B);
    cudaGetSymbolAddress((void**)&W1h, g_W1h);
    cudaGetSymbolAddress((void**)&W2h, g_W2h);
    cudaGetSymbolAddress((void**)&F, g_F);

    cudaFuncSetAttribute(mlp_layer<true, false>,
                         cudaFuncAttributeMaxDynamicSharedMemorySize, SMEM_TOTAL);
    cudaFuncSetAttribute(mlp_layer<false, true>,
                         cudaFuncAttributeMaxDynamicSharedMemorySize, SMEM_TOTAL);

    // layer 1: fp32 x + fp32 W (in-CTA convert + publish) -> fp16 B (+F if eps!=0)
    mlp_layer<true, false><<<GN / BM, 256, SMEM_TOTAL>>>(
        x, nullptr, nullptr, adj, W1, W2, nullptr, nullptr, W1h, W2h,
        b1, b2, eps, B, F);

    // layer 2: fp16 B + published fp16 W -> fp32 out
    mlp_layer<false, true><<<GN / BM, 256, SMEM_TOTAL>>>(
        nullptr, B, F, adj, nullptr, nullptr, W1h, W2h, nullptr, nullptr,
        b1, b2, eps, nullptr, out);
}